// round 6
// baseline (speedup 1.0000x reference)
#include <cuda_runtime.h>
#include <stdint.h>

#define BATCH 8
#define HW    4096
#define CDIM  384
#define KSEL  128

#define FEAT_N (BATCH * HW * CDIM)   // 12582912
#define MASK_N (BATCH * HW)          // 32768
#define BK_N   (BATCH * KSEL)        // 1024

// ---------------- scratch (device globals: no allocations allowed) ----------
__device__ float g_f1[FEAT_N];   // normalized, masked feature1
__device__ float g_f2[FEAT_N];   // normalized, masked feature2
__device__ float g_sq1[MASK_N];
__device__ float g_sq2[MASK_N];
// packed argmin state: high 32 bits = float bits of d (>=0), low 32 = index
__device__ unsigned long long g_key1[MASK_N];  // argmin over j (match1)
__device__ unsigned long long g_key2[MASK_N];  // argmin over i (match2)

// ---------------- init ------------------------------------------------------
__global__ void init_keys_kernel() {
    int t = blockIdx.x * blockDim.x + threadIdx.x;
    if (t < MASK_N) { g_key1[t] = ~0ULL; g_key2[t] = ~0ULL; }
}

// ---------------- normalize: f / ||f||, zero masked; record sum(y^2) --------
__global__ void normalize_kernel(const float* __restrict__ f,
                                 const int* __restrict__ mask, int which) {
    int token = blockIdx.x * 8 + (threadIdx.x >> 5);
    int lane  = threadIdx.x & 31;
    if (token >= MASK_N) return;
    const float* src = f + (size_t)token * CDIM;
    float v[12];
    float s = 0.f;
#pragma unroll
    for (int q = 0; q < 12; q++) { v[q] = src[lane + 32 * q]; s += v[q] * v[q]; }
#pragma unroll
    for (int o = 16; o; o >>= 1) s += __shfl_xor_sync(0xFFFFFFFFu, s, o);
    float norm = sqrtf(s);
    float m = (mask[token] > 0) ? 1.f : 0.f;
    float* dst = (which ? g_f2 : g_f1) + (size_t)token * CDIM;
    float sq = 0.f;
#pragma unroll
    for (int q = 0; q < 12; q++) {
        float y = m * (v[q] / norm);
        dst[lane + 32 * q] = y;
        sq += y * y;
    }
#pragma unroll
    for (int o = 16; o; o >>= 1) sq += __shfl_xor_sync(0xFFFFFFFFu, sq, o);
    if (lane == 0) (which ? g_sq2 : g_sq1)[token] = sq;
}

// ---------------- tiled GEMM + fused row/col argmin -------------------------
// CTA: 128x128 tile of D[b], 256 threads, 8x8 microtiles (stride-16 mapping).
__global__ void __launch_bounds__(256, 2)
argmin_kernel(const int* __restrict__ mask1, const int* __restrict__ mask2) {
    int bt = blockIdx.z, it = blockIdx.y, jt = blockIdx.x;
    __shared__ float As[32][129];
    __shared__ float Bs[32][129];
    __shared__ unsigned long long s_col[8][128];

    const float* A  = g_f1 + ((size_t)bt * HW + it * 128) * CDIM;
    const float* Bp = g_f2 + ((size_t)bt * HW + jt * 128) * CDIM;

    int tid = threadIdx.x;
    int tx = tid & 15, ty = tid >> 4;

    float acc[8][8];
#pragma unroll
    for (int v = 0; v < 8; v++)
#pragma unroll
        for (int u = 0; u < 8; u++) acc[v][u] = 0.f;

    for (int k0 = 0; k0 < CDIM; k0 += 32) {
#pragma unroll
        for (int r = 0; r < 4; r++) {
            int id = tid + r * 256;
            int row = id >> 3, kq = id & 7;
            float4 a4 = *(const float4*)(A  + (size_t)row * CDIM + k0 + kq * 4);
            As[kq * 4 + 0][row] = a4.x; As[kq * 4 + 1][row] = a4.y;
            As[kq * 4 + 2][row] = a4.z; As[kq * 4 + 3][row] = a4.w;
            float4 b4 = *(const float4*)(Bp + (size_t)row * CDIM + k0 + kq * 4);
            Bs[kq * 4 + 0][row] = b4.x; Bs[kq * 4 + 1][row] = b4.y;
            Bs[kq * 4 + 2][row] = b4.z; Bs[kq * 4 + 3][row] = b4.w;
        }
        __syncthreads();
#pragma unroll
        for (int kk = 0; kk < 32; kk++) {
            float a[8], b[8];
#pragma unroll
            for (int u = 0; u < 8; u++) {
                a[u] = As[kk][ty + 16 * u];
                b[u] = Bs[kk][tx + 16 * u];
            }
#pragma unroll
            for (int v = 0; v < 8; v++)
#pragma unroll
                for (int u = 0; u < 8; u++)
                    acc[v][u] = fmaf(a[v], b[u], acc[v][u]);
        }
        __syncthreads();
    }

    int   m1v[8], m2v[8];
    float sq1v[8], sq2v[8];
#pragma unroll
    for (int v = 0; v < 8; v++) {
        int i = it * 128 + ty + 16 * v;
        m1v[v]  = mask1[bt * HW + i];
        sq1v[v] = g_sq1[bt * HW + i];
    }
#pragma unroll
    for (int u = 0; u < 8; u++) {
        int j = jt * 128 + tx + 16 * u;
        m2v[u]  = mask2[bt * HW + j];
        sq2v[u] = g_sq2[bt * HW + j];
    }

    // d = sqrt(max(d2,0)) to match reference rounding (incl. tie collapse),
    // masked pairs -> BIG_DIST (1e7)
    float dval[8][8];
#pragma unroll
    for (int v = 0; v < 8; v++)
#pragma unroll
        for (int u = 0; u < 8; u++)
            dval[v][u] = (m1v[v] > 0 && m2v[u] > 0)
                ? sqrtf(fmaxf(sq1v[v] + sq2v[u] - 2.f * acc[v][u], 0.f))
                : 1.0e7f;

    // --- row argmin (over j) -> g_key1 ---
#pragma unroll
    for (int v = 0; v < 8; v++) {
        unsigned long long best = ~0ULL;
#pragma unroll
        for (int u = 0; u < 8; u++) {
            int j = jt * 128 + tx + 16 * u;
            unsigned long long key =
                ((unsigned long long)__float_as_uint(dval[v][u]) << 32) | (unsigned)j;
            best = key < best ? key : best;
        }
#pragma unroll
        for (int o = 1; o < 16; o <<= 1) {
            unsigned long long oth = __shfl_xor_sync(0xFFFFFFFFu, best, o);
            best = oth < best ? oth : best;
        }
        if (tx == 0)
            atomicMin(&g_key1[bt * HW + it * 128 + ty + 16 * v], best);
    }

    // --- col argmin (over i) -> g_key2 ---
#pragma unroll
    for (int u = 0; u < 8; u++) {
        unsigned long long best = ~0ULL;
#pragma unroll
        for (int v = 0; v < 8; v++) {
            int i = it * 128 + ty + 16 * v;
            unsigned long long key =
                ((unsigned long long)__float_as_uint(dval[v][u]) << 32) | (unsigned)i;
            best = key < best ? key : best;
        }
        unsigned long long oth = __shfl_xor_sync(0xFFFFFFFFu, best, 16);
        best = oth < best ? oth : best;
        if ((tid & 31) < 16) s_col[tid >> 5][tx + 16 * u] = best;
    }
    __syncthreads();
    if (tid < 128) {
        unsigned long long best = s_col[0][tid];
#pragma unroll
        for (int w = 1; w < 8; w++) {
            unsigned long long o = s_col[w][tid];
            best = o < best ? o : best;
        }
        atomicMin(&g_key2[bt * HW + jt * 128 + tid], best);
    }
}

// ---------------- cyclic diff + stable top-128 (bitonic) --------------------
// Output written as FLOAT32 (harness __output__ dtype): index values <= 4095
// are exactly representable.
__global__ void topk_kernel(const int* __restrict__ mask1, const int* __restrict__ mask2,
                            const int* __restrict__ backup1, const int* __restrict__ backup2,
                            float* __restrict__ out) {
    int b   = blockIdx.x >> 1;
    int dir = blockIdx.x & 1;
    const unsigned long long* keyF  = dir ? g_key2 : g_key1; // match_fwd
    const unsigned long long* keyBk = dir ? g_key1 : g_key2; // match_bwd
    const int* mSrc   = dir ? mask2   : mask1;
    const int* mDst   = dir ? mask1   : mask2;
    const int* backup = dir ? backup2 : backup1;

    __shared__ unsigned long long keys[HW];   // 32 KB
    __shared__ int s_cnt;
    int tid = threadIdx.x;                    // 512 threads
    if (tid == 0) s_cnt = 0;
    __syncthreads();

    int cnt = 0;
    for (int i = tid; i < HW; i += 512) {
        int srcm = mSrc[b * HW + i];
        cnt += (srcm > 0);
        int mf = (int)(keyF[b * HW + i] & 0xFFFFFFFFull);
        unsigned k32;
        if (srcm > 0 && mDst[b * HW + mf] > 0) {
            int cyc = (int)(keyBk[b * HW + mf] & 0xFFFFFFFFull);
            int dx = (cyc >> 6) - (i >> 6);   // x = idx / 64
            int dy = (cyc & 63) - (i & 63);   // y = idx % 64
            k32 = (unsigned)(dx * dx + dy * dy); // integer d2: same order/ties as fp32 sqrt
        } else {
            k32 = 0x7FFFFFFFu;                // > any real diff  (BIG_DIFF stand-in)
        }
        keys[i] = ((unsigned long long)k32 << 32) | (unsigned)i;
    }
#pragma unroll
    for (int o = 16; o; o >>= 1) cnt += __shfl_xor_sync(0xFFFFFFFFu, cnt, o);
    if ((tid & 31) == 0) atomicAdd(&s_cnt, cnt);
    __syncthreads();

    // bitonic sort ascending over (d2, index) — matches jax.lax.top_k stability
    for (int kk = 2; kk <= HW; kk <<= 1) {
        for (int jj = kk >> 1; jj > 0; jj >>= 1) {
            for (int i = tid; i < HW; i += 512) {
                int ixj = i ^ jj;
                if (ixj > i) {
                    unsigned long long a = keys[i], c = keys[ixj];
                    bool up = ((i & kk) == 0);
                    if ((a > c) == up) { keys[i] = c; keys[ixj] = a; }
                }
            }
            __syncthreads();
        }
    }

    bool useTop = (s_cnt >= KSEL);
    if (tid < KSEL) {
        int idx   = useTop ? (int)(keys[tid] & 0xFFFFFFFFull) : backup[b * KSEL + tid];
        int match = (int)(keyF[b * HW + idx] & 0xFFFFFFFFull);
        int base  = dir * (BATCH * KSEL * 2) + b * (KSEL * 2) + tid * 2;
        out[base]     = (float)idx;
        out[base + 1] = (float)match;
    }
}

// ---------------- launch ----------------------------------------------------
extern "C" void kernel_launch(void* const* d_in, const int* in_sizes, int n_in,
                              void* d_out, int out_size) {
    // Bind inputs by size; accept element counts OR byte counts (no collisions
    // between the 6 classes in either unit). Fall back to dict order.
    const float* f1 = nullptr; const float* f2 = nullptr;
    const int* mask1 = nullptr; const int* mask2 = nullptr;
    const int* bk1 = nullptr; const int* bk2 = nullptr;
    for (int i = 0; i < n_in; i++) {
        long long sz = in_sizes[i];
        if (sz == FEAT_N || sz == (long long)FEAT_N * 4) {
            if (!f1) f1 = (const float*)d_in[i]; else f2 = (const float*)d_in[i];
        } else if (sz == MASK_N || sz == (long long)MASK_N * 4) {
            if (!mask1) mask1 = (const int*)d_in[i]; else mask2 = (const int*)d_in[i];
        } else if (sz == BK_N || sz == (long long)BK_N * 4) {
            if (!bk1) bk1 = (const int*)d_in[i]; else bk2 = (const int*)d_in[i];
        }
    }
    if (!f1 || !f2 || !mask1 || !mask2 || !bk1 || !bk2) {
        // positional fallback: setup_inputs() dict order
        f1    = (const float*)d_in[0];
        f2    = (const float*)d_in[1];
        mask1 = (const int*)d_in[2];
        mask2 = (const int*)d_in[3];
        bk1   = (const int*)d_in[4];
        bk2   = (const int*)d_in[5];
    }
    float* out = (float*)d_out;

    init_keys_kernel<<<(MASK_N + 1023) / 1024, 1024>>>();
    normalize_kernel<<<MASK_N / 8, 256>>>(f1, mask1, 0);
    normalize_kernel<<<MASK_N / 8, 256>>>(f2, mask2, 1);
    dim3 grid(HW / 128, HW / 128, BATCH);
    argmin_kernel<<<grid, 256>>>(mask1, mask2);
    topk_kernel<<<BATCH * 2, 512>>>(mask1, mask2, bk1, bk2, out);
}